// round 10
// baseline (speedup 1.0000x reference)
#include <cuda_runtime.h>
#include <math.h>

#define P_MAX  32768
#define NCELLS 4096
#define SORT_BLOCKS  148
#define SORT_THREADS 1024
#define MAX_ITEMS ((P_MAX + NCELLS) / 2)

// ---------------- device scratch (no allocation allowed) --------------------
__device__ int    g_counts[NCELLS];
__device__ int    g_cursor[NCELLS];
__device__ int    g_start[NCELLS];
__device__ int    g_pairbase[NCELLS];
__device__ int    g_cell[P_MAX];
__device__ int    g_items[MAX_ITEMS + 64];   // item = (piA<<1) | has_second
__device__ int    g_nitems;
__device__ float4 g_pt[P_MAX];    // sorted (x0,x1,x2, bitcast(orig p))
__device__ float4 g_dir[P_MAX];   // sorted (d0,d1,d2, 0)
__device__ unsigned          g_bar_cnt;
__device__ volatile unsigned g_bar_gen;

// ---------------- helpers ---------------------------------------------------
__device__ __forceinline__ int cell_of(float x0, float x1, float x2) {
    float v0 = x0 / 0.1875f + 8.0f;
    float v1 = x1 / 0.1875f + 8.0f;
    float v2 = x2 / 0.1875f + 8.0f;
    int i0 = (int)v0; i0 = min(max(i0, 0), 15);
    int i1 = (int)v1; i1 = min(max(i1, 0), 15);
    int i2 = (int)v2; i2 = min(max(i2, 0), 15);
    return (i0 * 16 + i1) * 16 + i2;
}

__device__ __forceinline__ void gridbar() {
    __syncthreads();
    if (threadIdx.x == 0) {
        unsigned gen = g_bar_gen;
        __threadfence();
        unsigned arrived = atomicAdd(&g_bar_cnt, 1u);
        if (arrived == gridDim.x - 1) {
            g_bar_cnt = 0;
            __threadfence();
            g_bar_gen = gen + 1;
        } else {
            while (g_bar_gen == gen) { __nanosleep(64); }
            __threadfence();
        }
    }
    __syncthreads();
}

// ------- kernel 1: counting sort + pair items (persistent, wide) ------------
__global__ __launch_bounds__(SORT_THREADS) void k_sort(
    const float* __restrict__ x, const float* __restrict__ d, int P)
{
    int tid  = blockIdx.x * blockDim.x + threadIdx.x;
    int nthr = gridDim.x * blockDim.x;

    for (int c = tid; c < NCELLS; c += nthr) g_counts[c] = 0;
    gridbar();

    for (int p = tid; p < P; p += nthr) {
        int c = cell_of(x[3 * p], x[3 * p + 1], x[3 * p + 2]);
        g_cell[p] = c;
        atomicAdd(&g_counts[c], 1);
    }
    gridbar();

    if (blockIdx.x == 0) {            // two scans: 1024 thr x 4 cells
        __shared__ int s[SORT_THREADS];
        int t = threadIdx.x;
        int4 v = ((const int4*)g_counts)[t];
        int sum = v.x + v.y + v.z + v.w;
        s[t] = sum;
        __syncthreads();
        #pragma unroll
        for (int off = 1; off < SORT_THREADS; off <<= 1) {
            int u = (t >= off) ? s[t - off] : 0;
            __syncthreads();
            s[t] += u;
            __syncthreads();
        }
        int run = s[t] - sum;         // exclusive
        g_start[4 * t + 0] = run;               g_cursor[4 * t + 0] = run;
        g_start[4 * t + 1] = run + v.x;         g_cursor[4 * t + 1] = run + v.x;
        g_start[4 * t + 2] = run + v.x + v.y;   g_cursor[4 * t + 2] = run + v.x + v.y;
        g_start[4 * t + 3] = run + v.x + v.y + v.z;
        g_cursor[4 * t + 3] = run + v.x + v.y + v.z;

        // pair-count scan
        int p0 = (v.x + 1) >> 1, p1 = (v.y + 1) >> 1;
        int p2 = (v.z + 1) >> 1, p3 = (v.w + 1) >> 1;
        int psum = p0 + p1 + p2 + p3;
        __syncthreads();
        s[t] = psum;
        __syncthreads();
        #pragma unroll
        for (int off = 1; off < SORT_THREADS; off <<= 1) {
            int u = (t >= off) ? s[t - off] : 0;
            __syncthreads();
            s[t] += u;
            __syncthreads();
        }
        int prun = s[t] - psum;
        g_pairbase[4 * t + 0] = prun;
        g_pairbase[4 * t + 1] = prun + p0;
        g_pairbase[4 * t + 2] = prun + p0 + p1;
        g_pairbase[4 * t + 3] = prun + p0 + p1 + p2;
        if (t == SORT_THREADS - 1) g_nitems = s[t];
    }
    gridbar();

    // items (ordered) + scatter — independent arrays, same phase
    for (int c = tid; c < NCELLS; c += nthr) {
        int s0 = g_start[c], cnt = g_counts[c], base = g_pairbase[c];
        int np = cnt >> 1;
        for (int j = 0; j < np; j++) g_items[base + j] = ((s0 + 2 * j) << 1) | 1;
        if (cnt & 1) g_items[base + np] = (s0 + cnt - 1) << 1;
    }
    for (int p = tid; p < P; p += nthr) {
        int c = g_cell[p];
        int pos = atomicAdd(&g_cursor[c], 1);
        g_pt[pos]  = make_float4(x[3 * p], x[3 * p + 1], x[3 * p + 2], __int_as_float(p));
        g_dir[pos] = make_float4(d[3 * p], d[3 * p + 1], d[3 * p + 2], 0.0f);
    }
}

// -------- MLP micro-op: one float4 weight load feeds BOTH points ------------
__device__ __forceinline__ void fma4x2(float ha, float hb,
                                       const float4* __restrict__ w4,
                                       float* __restrict__ aA,
                                       float* __restrict__ aB) {
    float4 w = __ldg(w4);
    aA[0] = fmaf(ha, w.x, aA[0]); aA[1] = fmaf(ha, w.y, aA[1]);
    aA[2] = fmaf(ha, w.z, aA[2]); aA[3] = fmaf(ha, w.w, aA[3]);
    aB[0] = fmaf(hb, w.x, aB[0]); aB[1] = fmaf(hb, w.y, aB[1]);
    aB[2] = fmaf(hb, w.z, aB[2]); aB[3] = fmaf(hb, w.w, aB[3]);
}

// -------- kernel 2: MLP, 8 threads x (2 same-cell points), 64-reg diet ------
__global__ __launch_bounds__(256, 4) void k_mlp(
    const float* __restrict__ l1w, const float* __restrict__ l1b,
    const float* __restrict__ l2w, const float* __restrict__ l2b,
    const float* __restrict__ l3w, const float* __restrict__ l3b,
    const float* __restrict__ l4w, const float* __restrict__ l4b,
    const float* __restrict__ l5w, const float* __restrict__ l5b,
    float* __restrict__ out, int P)
{
    int t   = blockIdx.x * 256 + threadIdx.x;
    int it  = t >> 3;
    int sub = t & 7;
    if (it >= g_nitems) return;
    unsigned lanebase = ((unsigned)threadIdx.x & 31u) & ~7u;
    unsigned gm = 0xFFu << lanebase;

    int item = g_items[it];
    int piA = item >> 1;
    int piB = piA + (item & 1);            // same point if single-item

    int c, pmA, pmB;                       // p with mask packed in bit 31
    float accA[4], accB[4], prevA[4], prevB[4];

    // ======== layer 1: 63 -> 32, relu (xv released after this block) ========
    {
        float4 xvA = g_pt[piA], xvB = g_pt[piB];
        c = cell_of(xvA.x, xvA.y, xvA.z);
        bool mA = (fabsf(xvA.x) < 1.5f) && (fabsf(xvA.y) < 1.5f) && (fabsf(xvA.z) < 1.5f);
        bool mB = (fabsf(xvB.x) < 1.5f) && (fabsf(xvB.y) < 1.5f) && (fabsf(xvB.z) < 1.5f);
        pmA = __float_as_int(xvA.w) | (mA ? (1 << 31) : 0);
        pmB = __float_as_int(xvB.w) | (mB ? (1 << 31) : 0);

        const float4* b4 = (const float4*)(l1b + c * 32) + sub;
        float4 b0 = __ldg(b4);
        accA[0] = b0.x; accA[1] = b0.y; accA[2] = b0.z; accA[3] = b0.w;
        accB[0] = b0.x; accB[1] = b0.y; accB[2] = b0.z; accB[3] = b0.w;

        const float4* w1 = (const float4*)(l1w + (size_t)c * 2016) + sub;
        fma4x2(xvA.x, xvB.x, w1 + 0 * 8, accA, accB);
        fma4x2(xvA.y, xvB.y, w1 + 1 * 8, accA, accB);
        fma4x2(xvA.z, xvB.z, w1 + 2 * 8, accA, accB);
        float sA0 = sinf(xvA.x), cA0 = cosf(xvA.x);
        float sA1 = sinf(xvA.y), cA1 = cosf(xvA.y);
        float sA2 = sinf(xvA.z), cA2 = cosf(xvA.z);
        float sB0 = sinf(xvB.x), cB0 = cosf(xvB.x);
        float sB1 = sinf(xvB.y), cB1 = cosf(xvB.y);
        float sB2 = sinf(xvB.z), cB2 = cosf(xvB.z);
        #pragma unroll 1
        for (int j = 0; j < 10; j++) {
            const float4* wr = w1 + (3 + 6 * j) * 8;
            fma4x2(sA0, sB0, wr + 0 * 8, accA, accB);
            fma4x2(sA1, sB1, wr + 1 * 8, accA, accB);
            fma4x2(sA2, sB2, wr + 2 * 8, accA, accB);
            fma4x2(cA0, cB0, wr + 3 * 8, accA, accB);
            fma4x2(cA1, cB1, wr + 4 * 8, accA, accB);
            fma4x2(cA2, cB2, wr + 5 * 8, accA, accB);
            float n, m;
            n = 2.0f * sA0 * cA0; m = 1.0f - 2.0f * sA0 * sA0; sA0 = n; cA0 = m;
            n = 2.0f * sA1 * cA1; m = 1.0f - 2.0f * sA1 * sA1; sA1 = n; cA1 = m;
            n = 2.0f * sA2 * cA2; m = 1.0f - 2.0f * sA2 * sA2; sA2 = n; cA2 = m;
            n = 2.0f * sB0 * cB0; m = 1.0f - 2.0f * sB0 * sB0; sB0 = n; cB0 = m;
            n = 2.0f * sB1 * cB1; m = 1.0f - 2.0f * sB1 * sB1; sB1 = n; cB1 = m;
            n = 2.0f * sB2 * cB2; m = 1.0f - 2.0f * sB2 * sB2; sB2 = n; cB2 = m;
        }
        #pragma unroll
        for (int q = 0; q < 4; q++) {
            prevA[q] = fmaxf(accA[q], 0.0f);
            prevB[q] = fmaxf(accB[q], 0.0f);
        }
    }

    // ======== layer 2: 32 -> 33 (stride 33, scalar), relu; col32 = density ==
    float densA = 0.0f, densB = 0.0f;
    {
        int o0 = sub * 4;
        const float* base = l2w + (size_t)c * 1056 + o0;
        #pragma unroll
        for (int q = 0; q < 4; q++) {
            float bv = __ldg(l2b + c * 33 + o0 + q);
            accA[q] = bv; accB[q] = bv;
        }
        if (sub == 7) { float bv = __ldg(l2b + c * 33 + 32); densA = bv; densB = bv; }
        #pragma unroll 2
        for (int g = 0; g < 8; g++) {
            int src = lanebase + g;
            #pragma unroll
            for (int j = 0; j < 4; j++) {
                float ha = __shfl_sync(gm, prevA[j], src);
                float hb = __shfl_sync(gm, prevB[j], src);
                const float* wr = base + (g * 4 + j) * 33;
                float w0 = __ldg(wr + 0), w1 = __ldg(wr + 1);
                float w2 = __ldg(wr + 2), w3 = __ldg(wr + 3);
                accA[0] = fmaf(ha, w0, accA[0]); accB[0] = fmaf(hb, w0, accB[0]);
                accA[1] = fmaf(ha, w1, accA[1]); accB[1] = fmaf(hb, w1, accB[1]);
                accA[2] = fmaf(ha, w2, accA[2]); accB[2] = fmaf(hb, w2, accB[2]);
                accA[3] = fmaf(ha, w3, accA[3]); accB[3] = fmaf(hb, w3, accB[3]);
                if (sub == 7) {                       // o0=28 -> +4 = col 32
                    float wd = __ldg(wr + 4);
                    densA = fmaf(ha, wd, densA);
                    densB = fmaf(hb, wd, densB);
                }
            }
        }
        densA = fmaxf(densA, 0.0f);
        densB = fmaxf(densB, 0.0f);
        #pragma unroll
        for (int q = 0; q < 4; q++) {
            prevA[q] = fmaxf(accA[q], 0.0f);
            prevB[q] = fmaxf(accB[q], 0.0f);
        }
    }

    // ======== layer 3: 32 -> 32, NO activation ==============================
    {
        const float4* b4 = (const float4*)(l3b + c * 32) + sub;
        float4 b0 = __ldg(b4);
        accA[0] = b0.x; accA[1] = b0.y; accA[2] = b0.z; accA[3] = b0.w;
        accB[0] = b0.x; accB[1] = b0.y; accB[2] = b0.z; accB[3] = b0.w;
        const float4* w3 = (const float4*)(l3w + (size_t)c * 1024) + sub;
        #pragma unroll 2
        for (int g = 0; g < 8; g++) {
            int src = lanebase + g;
            #pragma unroll
            for (int j = 0; j < 4; j++) {
                float ha = __shfl_sync(gm, prevA[j], src);
                float hb = __shfl_sync(gm, prevB[j], src);
                fma4x2(ha, hb, w3 + (g * 4 + j) * 8, accA, accB);
            }
        }
        #pragma unroll
        for (int q = 0; q < 4; q++) { prevA[q] = accA[q]; prevB[q] = accB[q]; }
    }

    // ======== layer 4: 59 -> 32, relu (dir loaded HERE, not earlier) ========
    {
        const float4* b4 = (const float4*)(l4b + c * 32) + sub;
        float4 b0 = __ldg(b4);
        accA[0] = b0.x; accA[1] = b0.y; accA[2] = b0.z; accA[3] = b0.w;
        accB[0] = b0.x; accB[1] = b0.y; accB[2] = b0.z; accB[3] = b0.w;
        const float4* w4 = (const float4*)(l4w + (size_t)c * 1888) + sub;
        float4 dvA = g_dir[piA], dvB = g_dir[piB];
        #pragma unroll 2
        for (int g = 0; g < 8; g++) {
            int src = lanebase + g;
            #pragma unroll
            for (int j = 0; j < 4; j++) {
                float ha = __shfl_sync(gm, prevA[j], src);
                float hb = __shfl_sync(gm, prevB[j], src);
                fma4x2(ha, hb, w4 + (g * 4 + j) * 8, accA, accB);
            }
        }
        fma4x2(dvA.x, dvB.x, w4 + 32 * 8, accA, accB);
        fma4x2(dvA.y, dvB.y, w4 + 33 * 8, accA, accB);
        fma4x2(dvA.z, dvB.z, w4 + 34 * 8, accA, accB);
        float sA0 = sinf(dvA.x), cA0 = cosf(dvA.x);
        float sA1 = sinf(dvA.y), cA1 = cosf(dvA.y);
        float sA2 = sinf(dvA.z), cA2 = cosf(dvA.z);
        float sB0 = sinf(dvB.x), cB0 = cosf(dvB.x);
        float sB1 = sinf(dvB.y), cB1 = cosf(dvB.y);
        float sB2 = sinf(dvB.z), cB2 = cosf(dvB.z);
        #pragma unroll 1
        for (int j = 0; j < 4; j++) {
            const float4* wr = w4 + (35 + 6 * j) * 8;
            fma4x2(sA0, sB0, wr + 0 * 8, accA, accB);
            fma4x2(sA1, sB1, wr + 1 * 8, accA, accB);
            fma4x2(sA2, sB2, wr + 2 * 8, accA, accB);
            fma4x2(cA0, cB0, wr + 3 * 8, accA, accB);
            fma4x2(cA1, cB1, wr + 4 * 8, accA, accB);
            fma4x2(cA2, cB2, wr + 5 * 8, accA, accB);
            float n, m;
            n = 2.0f * sA0 * cA0; m = 1.0f - 2.0f * sA0 * sA0; sA0 = n; cA0 = m;
            n = 2.0f * sA1 * cA1; m = 1.0f - 2.0f * sA1 * sA1; sA1 = n; cA1 = m;
            n = 2.0f * sA2 * cA2; m = 1.0f - 2.0f * sA2 * sA2; sA2 = n; cA2 = m;
            n = 2.0f * sB0 * cB0; m = 1.0f - 2.0f * sB0 * sB0; sB0 = n; cB0 = m;
            n = 2.0f * sB1 * cB1; m = 1.0f - 2.0f * sB1 * sB1; sB1 = n; cB1 = m;
            n = 2.0f * sB2 * cB2; m = 1.0f - 2.0f * sB2 * sB2; sB2 = n; cB2 = m;
        }
        #pragma unroll
        for (int q = 0; q < 4; q++) {
            prevA[q] = fmaxf(accA[q], 0.0f);
            prevB[q] = fmaxf(accB[q], 0.0f);
        }
    }

    // ======== layer 5: 32 -> 3, sigmoid =====================================
    {
        int o = min(sub, 2);
        const float* w5 = l5w + c * 96 + o;
        float bv = __ldg(l5b + c * 3 + o);
        float a5A = bv, a5B = bv;
        #pragma unroll 2
        for (int g = 0; g < 8; g++) {
            int src = lanebase + g;
            #pragma unroll
            for (int j = 0; j < 4; j++) {
                float ha = __shfl_sync(gm, prevA[j], src);
                float hb = __shfl_sync(gm, prevB[j], src);
                float w = __ldg(w5 + (g * 4 + j) * 3);
                a5A = fmaf(ha, w, a5A);
                a5B = fmaf(hb, w, a5B);
            }
        }
        int pA = pmA & 0x7FFFFFFF, pB = pmB & 0x7FFFFFFF;
        bool mA = pmA < 0, mB = pmB < 0;
        if (sub < 3) {
            float cvA = 1.0f / (1.0f + expf(-a5A));
            float cvB = 1.0f / (1.0f + expf(-a5B));
            out[3 * pA + sub] = mA ? cvA : 0.0f;
            out[3 * pB + sub] = mB ? cvB : 0.0f;
        } else if (sub == 7) {
            out[3 * P + pA] = mA ? densA : 0.0f;
            out[3 * P + pB] = mB ? densB : 0.0f;
        }
    }
}

// ---------------- launch ----------------------------------------------------
extern "C" void kernel_launch(void* const* d_in, const int* in_sizes, int n_in,
                              void* d_out, int out_size) {
    const float* x   = (const float*)d_in[0];
    const float* d   = (const float*)d_in[1];
    const float* l1w = (const float*)d_in[2];
    const float* l1b = (const float*)d_in[3];
    const float* l2w = (const float*)d_in[4];
    const float* l2b = (const float*)d_in[5];
    const float* l3w = (const float*)d_in[6];
    const float* l3b = (const float*)d_in[7];
    const float* l4w = (const float*)d_in[8];
    const float* l4b = (const float*)d_in[9];
    const float* l5w = (const float*)d_in[10];
    const float* l5b = (const float*)d_in[11];
    float* out = (float*)d_out;

    int P = in_sizes[0] / 3;
    if (P > P_MAX) P = P_MAX;

    k_sort<<<SORT_BLOCKS, SORT_THREADS>>>(x, d, P);
    int maxItems = (P + NCELLS) / 2;           // >= device g_nitems always
    int threads  = maxItems * 8;
    k_mlp<<<(threads + 255) / 256, 256>>>(l1w, l1b, l2w, l2b, l3w, l3b,
                                          l4w, l4b, l5w, l5b, out, P);
}